// round 5
// baseline (speedup 1.0000x reference)
#include <cuda_runtime.h>
#include <cstdint>

// ---------------------------------------------------------------------------
// Problem constants
// ---------------------------------------------------------------------------
#define N_ROWS 16384      // 64 * 256
#define N_FEAT 2048
#define N_BINS 32
#define NSTRIPE 64
#define RPS (N_ROWS / NSTRIPE)     // 256 rows per stripe
#define TBL 65536
#define NTILE 128                  // 128-row tiles
#define NKQ 4                      // K split into quarters (512 cols each)
// project smem: RP' quarter (256 kk * 32 * 4B) + offset (32 f) + pad
#define PROJ_SMEM (256*32*4 + 128)   // 32896

// ---------------------------------------------------------------------------
// Scratch (static device globals; no runtime allocation)
// ---------------------------------------------------------------------------
__device__ float              g_psum[NSTRIPE * N_FEAT];
__device__ float              g_psq [NSTRIPE * N_FEAT];
__device__ float              g_isig[N_FEAT];
__device__ float              g_m2  [N_FEAT];              // mean * isig
__device__ float              g_off [N_BINS];              // m2 . RP
__device__ unsigned int       g_rppack[1024 * 32];         // bf16x2 isig*RP, swizzled
__device__ float              g_part[NKQ * N_ROWS * N_BINS]; // split-K partials
__device__ unsigned int       g_tilecnt[NTILE];            // arrival counters
__device__ unsigned int       g_hash[N_ROWS];
__device__ unsigned int       g_slot[N_ROWS];
__device__ unsigned long long g_tkey[TBL];
__device__ unsigned int       g_tcnt[TBL];

// ---------------------------------------------------------------------------
// Helpers
// ---------------------------------------------------------------------------
__device__ __forceinline__ unsigned packbf(float lo, float hi) {
    unsigned d;
    asm("cvt.rn.bf16x2.f32 %0, %1, %2;" : "=r"(d) : "f"(hi), "f"(lo));
    return d;
}

__device__ __forceinline__ void mma16816(float* c,
                                         unsigned a0, unsigned a1, unsigned a2, unsigned a3,
                                         unsigned b0, unsigned b1) {
    asm volatile(
        "mma.sync.aligned.m16n8k16.row.col.f32.bf16.bf16.f32 "
        "{%0,%1,%2,%3}, {%4,%5,%6,%7}, {%8,%9}, {%0,%1,%2,%3};"
        : "+f"(c[0]), "+f"(c[1]), "+f"(c[2]), "+f"(c[3])
        : "r"(a0), "r"(a1), "r"(a2), "r"(a3), "r"(b0), "r"(b1));
}

__device__ __forceinline__ void table_insert(int i, unsigned h) {
    unsigned long long key = ((unsigned long long)h << 6) | (unsigned long long)(i & 63);
    unsigned long long m = key * 0x9E3779B97F4A7C15ULL;
    unsigned s = (unsigned)(m >> 48);   // 16-bit slot
    for (;;) {
        unsigned long long prev = atomicCAS(&g_tkey[s], ~0ULL, key);
        if (prev == ~0ULL || prev == key) {
            atomicAdd(&g_tcnt[s], 1u);
            g_slot[i] = s;
            return;
        }
        s = (s + 1) & (TBL - 1);
    }
}

// ---------------------------------------------------------------------------
// Kernel 1 (fused): column partial sums + table/counter init.
// ---------------------------------------------------------------------------
__global__ void k_pre(const float* __restrict__ x) {
    int b = blockIdx.x;
    if (b < 512) {
        int colblk = b & 7, stripe = b >> 3;
        int col = colblk * 256 + threadIdx.x;
        const float* p = x + (size_t)(stripe * RPS) * N_FEAT + col;
        float s = 0.f, q = 0.f;
#pragma unroll 16
        for (int r = 0; r < RPS; r++) {
            float v = p[(size_t)r * N_FEAT];
            s += v;
            q = fmaf(v, v, q);
        }
        g_psum[stripe * N_FEAT + col] = s;
        g_psq [stripe * N_FEAT + col] = q;
    } else {
        int i = (b - 512) * 256 + threadIdx.x;
        g_tkey[i] = ~0ULL;
        g_tcnt[i] = 0u;
        if (b == 512 && threadIdx.x < NTILE) g_tilecnt[threadIdx.x] = 0u;
    }
}

// ---------------------------------------------------------------------------
// Kernel 2: finalize RunningMeanStd -> isig, mean*isig
// ---------------------------------------------------------------------------
__global__ void k_stats() {
    __shared__ float ss[8][32], sq[8][32];
    int c = threadIdx.x & 31, g = threadIdx.x >> 5;
    int col = blockIdx.x * 32 + c;
    float s = 0.f, q = 0.f;
#pragma unroll
    for (int st = g; st < NSTRIPE; st += 8) {
        s += g_psum[st * N_FEAT + col];
        q += g_psq [st * N_FEAT + col];
    }
    ss[g][c] = s; sq[g][c] = q;
    __syncthreads();
    if (g == 0) {
#pragma unroll
        for (int j = 1; j < 8; j++) { s += ss[j][c]; q += sq[j][c]; }
        const float n = 16384.0f;
        float bm = s / n;
        float bv = (q - bm * bm * n) / (n - 1.0f);       // unbiased variance
        const double nd = 16384.0, totd = 1e-4 + nd;
        float mean = bm * (float)(nd / totd);
        float m2v  = (1e-4f + bv * 16384.0f) + (bm * bm) * (float)(1e-4 * nd / totd);
        float var  = m2v / (float)totd;
        float isg  = 1.0f / sqrtf(var + 1e-8f);
        g_isig[col] = isg;
        g_m2[col]   = mean * isg;
    }
}

// ---------------------------------------------------------------------------
// Kernel 3: RP' = isig*RP packed bf16x2 swizzled (blocks 0..127);
//           offset[b] = sum_k m2[k]*RP[k,b] (block 128).
// ---------------------------------------------------------------------------
__global__ void k_scale(const float* __restrict__ rp) {
    if (blockIdx.x < 128) {
        int idx = blockIdx.x * 256 + threadIdx.x;  // 0..32767
        int kk  = idx >> 5;                        // k-pair index 0..1023
        int col = idx & 31;
        float lo = rp[(2 * kk)     * N_BINS + col] * g_isig[2 * kk];
        float hi = rp[(2 * kk + 1) * N_BINS + col] * g_isig[2 * kk + 1];
        int scol = col ^ ((kk & 3) << 3);
        g_rppack[kk * 32 + scol] = packbf(lo, hi);
    } else {
        __shared__ float red[8][32];
        int b = threadIdx.x & 31, part = threadIdx.x >> 5;   // 8 parts x 256 k
        float s = 0.f;
        for (int k = part * 256; k < part * 256 + 256; k++)
            s = fmaf(g_m2[k], rp[k * N_BINS + b], s);
        red[part][b] = s;
        __syncthreads();
        if (part == 0) {
#pragma unroll
            for (int j = 1; j < 8; j++) s += red[j][b];
            g_off[b] = s;
        }
    }
}

// ---------------------------------------------------------------------------
// Kernel 4: quarter-K raw-x bf16 mma projection -> fp32 partials -> (last
// arriving quarter per tile) combine + offset + sign hash + table insert.
//   512 blocks: tile = bid>>2, kq = bid&3. 32KB smem -> 3 blocks/SM (regs).
// ---------------------------------------------------------------------------
__global__ void __launch_bounds__(256, 3) k_project(const float* __restrict__ x) {
    extern __shared__ unsigned int smem[];          // [0,8192): RP' quarter
    float* soff = (float*)(smem + 8192);            // [32]
    __shared__ int s_last;

    int tile = blockIdx.x >> 2;
    int kq   = blockIdx.x & 3;
    int kbase = kq * 512;

    const unsigned* rpsrc = g_rppack + kq * 256 * 32;   // swizzle parity kept
    for (int idx = threadIdx.x; idx < 8192; idx += 256) smem[idx] = rpsrc[idx];
    if (threadIdx.x < 32) soff[threadIdx.x] = g_off[threadIdx.x];
    __syncthreads();

    int warp = threadIdx.x >> 5, lane = threadIdx.x & 31;
    int q = lane & 3, r = lane >> 2;
    int row0 = tile * 128 + warp * 16;

    const float* xa = x + (size_t)(row0 + r) * N_FEAT + kbase + 2 * q;
    const float* xb = xa + 8 * (size_t)N_FEAT;

    float acc[4][4];
#pragma unroll
    for (int t = 0; t < 4; t++)
#pragma unroll
        for (int c = 0; c < 4; c++) acc[t][c] = 0.f;

    unsigned scol[4];
#pragma unroll
    for (int t = 0; t < 4; t++) scol[t] = (unsigned)((t * 8 + r) ^ (q << 3));

#pragma unroll 4
    for (int k = 0; k < 512; k += 16) {
        float2 va = *(const float2*)(xa + k);
        float2 vb = *(const float2*)(xa + k + 8);
        float2 vc = *(const float2*)(xb + k);
        float2 vd = *(const float2*)(xb + k + 8);

        unsigned a0 = packbf(va.x, va.y);
        unsigned a2 = packbf(vb.x, vb.y);
        unsigned a1 = packbf(vc.x, vc.y);
        unsigned a3 = packbf(vd.x, vd.y);

        int kk = (k >> 1) + q;                      // kk&3 == q preserved
#pragma unroll
        for (int t = 0; t < 4; t++) {
            unsigned b0 = smem[kk * 32 + scol[t]];
            unsigned b1 = smem[(kk + 4) * 32 + scol[t]];
            mma16816(acc[t], a0, a1, a2, a3, b0, b1);
        }
    }

    // publish my quarter's partials
    float* dst = g_part + (size_t)kq * N_ROWS * N_BINS;
    int rowA = row0 + r, rowB = rowA + 8;
#pragma unroll
    for (int t = 0; t < 4; t++) {
        int cb = t * 8 + 2 * q;
        *(float2*)(dst + (size_t)rowA * N_BINS + cb) = make_float2(acc[t][0], acc[t][1]);
        *(float2*)(dst + (size_t)rowB * N_BINS + cb) = make_float2(acc[t][2], acc[t][3]);
    }
    __threadfence();
    if (threadIdx.x == 0) s_last = (int)atomicAdd(&g_tilecnt[tile], 1u);
    __syncthreads();
    if (s_last != NKQ - 1) return;    // earlier arrivals are done
    __threadfence();                  // make peers' partials visible

    // last-arriving quarter: add 3 peer partials (L2), subtract offset, sign
    unsigned mlo = 0u, mhi = 0u;
#pragma unroll
    for (int t = 0; t < 4; t++) {
        int cb = t * 8 + 2 * q;
        float sA0 = acc[t][0], sA1 = acc[t][1];
        float sB0 = acc[t][2], sB1 = acc[t][3];
#pragma unroll
        for (int o = 0; o < NKQ; o++) {
            if (o == kq) continue;
            const float* src = g_part + (size_t)o * N_ROWS * N_BINS;
            float2 pa = *(const float2*)(src + (size_t)rowA * N_BINS + cb);
            float2 pb = *(const float2*)(src + (size_t)rowB * N_BINS + cb);
            sA0 += pa.x; sA1 += pa.y;
            sB0 += pb.x; sB1 += pb.y;
        }
        float o0 = soff[cb], o1 = soff[cb + 1];
        mlo |= ((sA0 - o0) > 0.f ? 1u : 0u) << cb;
        mlo |= ((sA1 - o1) > 0.f ? 1u : 0u) << (cb + 1);
        mhi |= ((sB0 - o0) > 0.f ? 1u : 0u) << cb;
        mhi |= ((sB1 - o1) > 0.f ? 1u : 0u) << (cb + 1);
    }
    mlo |= __shfl_xor_sync(0xffffffffu, mlo, 1);
    mlo |= __shfl_xor_sync(0xffffffffu, mlo, 2);
    mhi |= __shfl_xor_sync(0xffffffffu, mhi, 1);
    mhi |= __shfl_xor_sync(0xffffffffu, mhi, 2);

    if (q == 0) {
        g_hash[rowA] = mlo;
        g_hash[rowB] = mhi;
        table_insert(rowA, mlo);
        table_insert(rowB, mhi);
    }
}

// ---------------------------------------------------------------------------
// Kernel 5: rewards. Unique keys -> 1.0; rare duplicates get exact rank.
// ---------------------------------------------------------------------------
__global__ void k_final(float* __restrict__ out) {
    int i = blockIdx.x * 128 + threadIdx.x;
    unsigned s = g_slot[i];
    float v = 1.0f;
    if (g_tcnt[s] != 1u) {
        unsigned long long my = ((unsigned long long)g_hash[i] << 6) | (unsigned long long)(i & 63);
        int c = 1;
        for (int j = 0; j < i; j++) {
            unsigned long long kj = ((unsigned long long)g_hash[j] << 6) | (unsigned long long)(j & 63);
            c += (kj == my) ? 1 : 0;
        }
        v = 1.0f / sqrtf((float)c);
    }
    out[i] = v;
}

// ---------------------------------------------------------------------------
// Launch
// ---------------------------------------------------------------------------
extern "C" void kernel_launch(void* const* d_in, const int* in_sizes, int n_in,
                              void* d_out, int out_size) {
    const float* x  = (const float*)d_in[0];
    const float* rp = (const float*)d_in[1];
    if (in_sizes[0] == N_FEAT * N_BINS) {   // defensive: swap if order differs
        const float* t = x; x = rp; rp = t;
    }
    float* out = (float*)d_out;

    cudaFuncSetAttribute(k_project, cudaFuncAttributeMaxDynamicSharedMemorySize, PROJ_SMEM);

    k_pre    <<<768, 256>>>(x);
    k_stats  <<<64, 256>>>();
    k_scale  <<<129, 256>>>(rp);
    k_project<<<512, 256, PROJ_SMEM>>>(x);
    k_final  <<<128, 128>>>(out);
}

// round 6
// speedup vs baseline: 1.0289x; 1.0289x over previous
#include <cuda_runtime.h>
#include <cstdint>

// ---------------------------------------------------------------------------
// Problem constants
// ---------------------------------------------------------------------------
#define N_ROWS 16384      // 64 * 256
#define N_FEAT 2048
#define N_BINS 32
#define NSTRIPE 128
#define RPS (N_ROWS / NSTRIPE)     // 128 rows per stripe
#define TBL 65536
#define NTILE 128                  // 128-row tiles
#define NKQ 4                      // K split into quarters (512 cols each)
// project smem: RP' quarter (256 kk * 32 * 4B) + offset (32 f) + pad
#define PROJ_SMEM (256*32*4 + 128)   // 32896

// ---------------------------------------------------------------------------
// Scratch (static device globals; no runtime allocation)
// ---------------------------------------------------------------------------
__device__ unsigned int       g_xpack[(size_t)N_ROWS * 1024]; // bf16x2 x, permuted
__device__ float              g_psum[NSTRIPE * N_FEAT];
__device__ float              g_psq [NSTRIPE * N_FEAT];
__device__ float              g_isig[N_FEAT];
__device__ float              g_m2  [N_FEAT];              // mean * isig
__device__ float              g_off [N_BINS];              // m2 . RP
__device__ unsigned int       g_rppack[1024 * 32];         // bf16x2 isig*RP, swizzled
__device__ float              g_part[NKQ * N_ROWS * N_BINS]; // split-K partials
__device__ unsigned int       g_tilecnt[NTILE];            // arrival counters
__device__ unsigned int       g_hash[N_ROWS];
__device__ unsigned int       g_slot[N_ROWS];
__device__ unsigned long long g_tkey[TBL];
__device__ unsigned int       g_tcnt[TBL];

// ---------------------------------------------------------------------------
// Helpers
// ---------------------------------------------------------------------------
__device__ __forceinline__ unsigned packbf(float lo, float hi) {
    unsigned d;
    asm("cvt.rn.bf16x2.f32 %0, %1, %2;" : "=r"(d) : "f"(hi), "f"(lo));
    return d;
}

__device__ __forceinline__ void mma16816(float* c,
                                         unsigned a0, unsigned a1, unsigned a2, unsigned a3,
                                         unsigned b0, unsigned b1) {
    asm volatile(
        "mma.sync.aligned.m16n8k16.row.col.f32.bf16.bf16.f32 "
        "{%0,%1,%2,%3}, {%4,%5,%6,%7}, {%8,%9}, {%0,%1,%2,%3};"
        : "+f"(c[0]), "+f"(c[1]), "+f"(c[2]), "+f"(c[3])
        : "r"(a0), "r"(a1), "r"(a2), "r"(a3), "r"(b0), "r"(b1));
}

__device__ __forceinline__ void table_insert(int i, unsigned h) {
    unsigned long long key = ((unsigned long long)h << 6) | (unsigned long long)(i & 63);
    unsigned long long m = key * 0x9E3779B97F4A7C15ULL;
    unsigned s = (unsigned)(m >> 48);   // 16-bit slot
    for (;;) {
        unsigned long long prev = atomicCAS(&g_tkey[s], ~0ULL, key);
        if (prev == ~0ULL || prev == key) {
            atomicAdd(&g_tcnt[s], 1u);
            g_slot[i] = s;
            return;
        }
        s = (s + 1) & (TBL - 1);
    }
}

// ---------------------------------------------------------------------------
// Kernel 1 (fused): column partial sums + bf16 permuted pack + table init.
//   blocks [0,512): stats+pack, thread owns a column PAIR over 128 rows.
//   blocks [512,768): hash-table / counter init.
// Permutation: pair index P, group=P>>4, p=P&15, m=((p&3)<<2)|(p>>2) so that
// k_project lane q's uint4 at group*16+4q = pairs (2q, 2q+8, 2q+16, 2q+24).
// ---------------------------------------------------------------------------
__global__ void k_pre(const float* __restrict__ x) {
    int b = blockIdx.x;
    if (b < 512) {
        int colblk = b & 3, stripe = b >> 2;
        int P = colblk * 256 + threadIdx.x;          // pair index 0..1023
        int group = P >> 4, p = P & 15;
        int permP = (group << 4) | (((p & 3) << 2) | (p >> 2));
        int row0 = stripe * RPS;
        const float2* src = (const float2*)(x + (size_t)row0 * N_FEAT) + P;
        unsigned* dst = g_xpack + (size_t)row0 * 1024 + permP;
        float s0 = 0.f, q0 = 0.f, s1 = 0.f, q1 = 0.f;
#pragma unroll 8
        for (int r = 0; r < RPS; r++) {
            float2 v = src[(size_t)r * 1024];
            s0 += v.x; q0 = fmaf(v.x, v.x, q0);
            s1 += v.y; q1 = fmaf(v.y, v.y, q1);
            dst[(size_t)r * 1024] = packbf(v.x, v.y);
        }
        *(float2*)(g_psum + stripe * N_FEAT + 2 * P) = make_float2(s0, s1);
        *(float2*)(g_psq  + stripe * N_FEAT + 2 * P) = make_float2(q0, q1);
    } else {
        int i = (b - 512) * 256 + threadIdx.x;
        g_tkey[i] = ~0ULL;
        g_tcnt[i] = 0u;
        if (b == 512 && threadIdx.x < NTILE) g_tilecnt[threadIdx.x] = 0u;
    }
}

// ---------------------------------------------------------------------------
// Kernel 2: finalize RunningMeanStd -> isig, mean*isig
// ---------------------------------------------------------------------------
__global__ void k_stats() {
    __shared__ float ss[8][32], sq[8][32];
    int c = threadIdx.x & 31, g = threadIdx.x >> 5;
    int col = blockIdx.x * 32 + c;
    float s = 0.f, q = 0.f;
#pragma unroll
    for (int st = g; st < NSTRIPE; st += 8) {
        s += g_psum[st * N_FEAT + col];
        q += g_psq [st * N_FEAT + col];
    }
    ss[g][c] = s; sq[g][c] = q;
    __syncthreads();
    if (g == 0) {
#pragma unroll
        for (int j = 1; j < 8; j++) { s += ss[j][c]; q += sq[j][c]; }
        const float n = 16384.0f;
        float bm = s / n;
        float bv = (q - bm * bm * n) / (n - 1.0f);       // unbiased variance
        const double nd = 16384.0, totd = 1e-4 + nd;
        float mean = bm * (float)(nd / totd);
        float m2v  = (1e-4f + bv * 16384.0f) + (bm * bm) * (float)(1e-4 * nd / totd);
        float var  = m2v / (float)totd;
        float isg  = 1.0f / sqrtf(var + 1e-8f);
        g_isig[col] = isg;
        g_m2[col]   = mean * isg;
    }
}

// ---------------------------------------------------------------------------
// Kernel 3: RP' = isig*RP packed bf16x2 swizzled (blocks 0..127);
//           offset[b] = sum_k m2[k]*RP[k,b] (block 128, deterministic).
// ---------------------------------------------------------------------------
__global__ void k_scale(const float* __restrict__ rp) {
    if (blockIdx.x < 128) {
        int idx = blockIdx.x * 256 + threadIdx.x;  // 0..32767
        int kk  = idx >> 5;                        // k-pair index 0..1023
        int col = idx & 31;
        float lo = rp[(2 * kk)     * N_BINS + col] * g_isig[2 * kk];
        float hi = rp[(2 * kk + 1) * N_BINS + col] * g_isig[2 * kk + 1];
        int scol = col ^ ((kk & 3) << 3);
        g_rppack[kk * 32 + scol] = packbf(lo, hi);
    } else {
        __shared__ float red[8][32];
        int b = threadIdx.x & 31, part = threadIdx.x >> 5;   // 8 parts x 256 k
        float s = 0.f;
        for (int k = part * 256; k < part * 256 + 256; k++)
            s = fmaf(g_m2[k], rp[k * N_BINS + b], s);
        red[part][b] = s;
        __syncthreads();
        if (part == 0) {
#pragma unroll
            for (int j = 1; j < 8; j++) s += red[j][b];
            g_off[b] = s;
        }
    }
}

// ---------------------------------------------------------------------------
// Kernel 4: quarter-K bf16 mma projection from pre-packed x -> fp32 partials
// -> (last arriving quarter per tile) combine + offset + sign hash + insert.
//   512 blocks: tile = bid>>2, kq = bid&3. 32KB smem.
// ---------------------------------------------------------------------------
__global__ void __launch_bounds__(256, 4) k_project() {
    extern __shared__ unsigned int smem[];          // [0,8192): RP' quarter
    float* soff = (float*)(smem + 8192);            // [32]
    __shared__ int s_last;

    int tile = blockIdx.x >> 2;
    int kq   = blockIdx.x & 3;

    const unsigned* rpsrc = g_rppack + kq * 256 * 32;   // swizzle parity kept
    for (int idx = threadIdx.x; idx < 8192; idx += 256) smem[idx] = rpsrc[idx];
    if (threadIdx.x < 32) soff[threadIdx.x] = g_off[threadIdx.x];
    __syncthreads();

    int warp = threadIdx.x >> 5, lane = threadIdx.x & 31;
    int q = lane & 3, r = lane >> 2;
    int row0 = tile * 128 + warp * 16;
    int rowA = row0 + r, rowB = rowA + 8;

    // uint4 view of permuted-packed x: row stride = 256 uint4; quarter base
    // group = kq*16; lane q owns uint4 slot q of each 32-col group.
    const uint4* xpA = (const uint4*)g_xpack + (size_t)rowA * 256 + kq * 64 + q;
    const uint4* xpB = (const uint4*)g_xpack + (size_t)rowB * 256 + kq * 64 + q;

    float acc[4][4];
#pragma unroll
    for (int t = 0; t < 4; t++)
#pragma unroll
        for (int c = 0; c < 4; c++) acc[t][c] = 0.f;

    unsigned scol[4];
#pragma unroll
    for (int t = 0; t < 4; t++) scol[t] = (unsigned)((t * 8 + r) ^ (q << 3));

#pragma unroll 4
    for (int g = 0; g < 16; g++) {                  // 16 groups of 32 cols
        uint4 va = xpA[g * 4];                      // pairs 2q,2q+8,2q+16,2q+24 row A
        uint4 vb = xpB[g * 4];                      // same, row B

        int kk1 = g * 16 + q;                       // (kk&3)==q preserved
#pragma unroll
        for (int t = 0; t < 4; t++) {
            unsigned b0 = smem[kk1 * 32 + scol[t]];
            unsigned b1 = smem[(kk1 + 4) * 32 + scol[t]];
            mma16816(acc[t], va.x, vb.x, va.y, vb.y, b0, b1);
        }
        int kk2 = kk1 + 8;
#pragma unroll
        for (int t = 0; t < 4; t++) {
            unsigned b0 = smem[kk2 * 32 + scol[t]];
            unsigned b1 = smem[(kk2 + 4) * 32 + scol[t]];
            mma16816(acc[t], va.z, vb.z, va.w, vb.w, b0, b1);
        }
    }

    // publish my quarter's partials
    float* dst = g_part + (size_t)kq * N_ROWS * N_BINS;
#pragma unroll
    for (int t = 0; t < 4; t++) {
        int cb = t * 8 + 2 * q;
        *(float2*)(dst + (size_t)rowA * N_BINS + cb) = make_float2(acc[t][0], acc[t][1]);
        *(float2*)(dst + (size_t)rowB * N_BINS + cb) = make_float2(acc[t][2], acc[t][3]);
    }
    __threadfence();
    if (threadIdx.x == 0) s_last = (int)atomicAdd(&g_tilecnt[tile], 1u);
    __syncthreads();
    if (s_last != NKQ - 1) return;    // earlier arrivals are done
    __threadfence();                  // make peers' partials visible

    // last-arriving quarter: add 3 peer partials (L2), subtract offset, sign
    unsigned mlo = 0u, mhi = 0u;
#pragma unroll
    for (int t = 0; t < 4; t++) {
        int cb = t * 8 + 2 * q;
        float sA0 = acc[t][0], sA1 = acc[t][1];
        float sB0 = acc[t][2], sB1 = acc[t][3];
#pragma unroll
        for (int o = 0; o < NKQ; o++) {
            if (o == kq) continue;
            const float* src = g_part + (size_t)o * N_ROWS * N_BINS;
            float2 pa = *(const float2*)(src + (size_t)rowA * N_BINS + cb);
            float2 pb = *(const float2*)(src + (size_t)rowB * N_BINS + cb);
            sA0 += pa.x; sA1 += pa.y;
            sB0 += pb.x; sB1 += pb.y;
        }
        float o0 = soff[cb], o1 = soff[cb + 1];
        mlo |= ((sA0 - o0) > 0.f ? 1u : 0u) << cb;
        mlo |= ((sA1 - o1) > 0.f ? 1u : 0u) << (cb + 1);
        mhi |= ((sB0 - o0) > 0.f ? 1u : 0u) << cb;
        mhi |= ((sB1 - o1) > 0.f ? 1u : 0u) << (cb + 1);
    }
    mlo |= __shfl_xor_sync(0xffffffffu, mlo, 1);
    mlo |= __shfl_xor_sync(0xffffffffu, mlo, 2);
    mhi |= __shfl_xor_sync(0xffffffffu, mhi, 1);
    mhi |= __shfl_xor_sync(0xffffffffu, mhi, 2);

    if (q == 0) {
        g_hash[rowA] = mlo;
        g_hash[rowB] = mhi;
        table_insert(rowA, mlo);
        table_insert(rowB, mhi);
    }
}

// ---------------------------------------------------------------------------
// Kernel 5: rewards. Unique keys -> 1.0; rare duplicates get exact rank.
// ---------------------------------------------------------------------------
__global__ void k_final(float* __restrict__ out) {
    int i = blockIdx.x * 128 + threadIdx.x;
    unsigned s = g_slot[i];
    float v = 1.0f;
    if (g_tcnt[s] != 1u) {
        unsigned long long my = ((unsigned long long)g_hash[i] << 6) | (unsigned long long)(i & 63);
        int c = 1;
        for (int j = 0; j < i; j++) {
            unsigned long long kj = ((unsigned long long)g_hash[j] << 6) | (unsigned long long)(j & 63);
            c += (kj == my) ? 1 : 0;
        }
        v = 1.0f / sqrtf((float)c);
    }
    out[i] = v;
}

// ---------------------------------------------------------------------------
// Launch
// ---------------------------------------------------------------------------
extern "C" void kernel_launch(void* const* d_in, const int* in_sizes, int n_in,
                              void* d_out, int out_size) {
    const float* x  = (const float*)d_in[0];
    const float* rp = (const float*)d_in[1];
    if (in_sizes[0] == N_FEAT * N_BINS) {   // defensive: swap if order differs
        const float* t = x; x = rp; rp = t;
    }
    float* out = (float*)d_out;

    cudaFuncSetAttribute(k_project, cudaFuncAttributeMaxDynamicSharedMemorySize, PROJ_SMEM);

    k_pre    <<<768, 256>>>(x);
    k_stats  <<<64, 256>>>();
    k_scale  <<<129, 256>>>(rp);
    k_project<<<512, 256, PROJ_SMEM>>>();
    k_final  <<<128, 128>>>(out);
}

// round 8
// speedup vs baseline: 1.0549x; 1.0252x over previous
#include <cuda_runtime.h>
#include <cstdint>

// ---------------------------------------------------------------------------
// Problem constants
// ---------------------------------------------------------------------------
#define N_ROWS 16384      // 64 * 256
#define N_FEAT 2048
#define N_BINS 32
#define NSTRIPE 256
#define RPS (N_ROWS / NSTRIPE)     // 64 rows per stripe
#define TBL 65536
#define NTILE 128                  // 128-row tiles
#define NKQ 4                      // K split into quarters (512 cols each)
#define NG 64                      // 32-col groups over full K
#define NT16 (N_ROWS / 16)         // 1024 16-row fragments

// ---------------------------------------------------------------------------
// Scratch (static device globals; no runtime allocation)
// ---------------------------------------------------------------------------
__device__ unsigned int       g_xpack8[(size_t)NT16 * NG * 32 * 4]; // e4m3 x, frag order (32MB)
__device__ float              g_psum[NSTRIPE * N_FEAT];
__device__ float              g_psq [NSTRIPE * N_FEAT];
__device__ float              g_isig[N_FEAT];
__device__ float              g_m2  [N_FEAT];              // mean * isig
__device__ float              g_off [N_BINS];              // 256 * (m2 . RP)
__device__ unsigned int       g_rppack8[512 * 32];         // e4m3x4 256*isig*RP, swizzled
__device__ float              g_part[NKQ * N_ROWS * N_BINS]; // split-K partials
__device__ unsigned int       g_tilecnt[NTILE];            // arrival counters
__device__ unsigned int       g_hash[N_ROWS];
__device__ unsigned int       g_slot[N_ROWS];
__device__ unsigned long long g_tkey[TBL];
__device__ unsigned int       g_tcnt[TBL];

// ---------------------------------------------------------------------------
// Helpers
// ---------------------------------------------------------------------------
// pack 4 floats to e4m3x4, byte0 = f0 (lowest k)
__device__ __forceinline__ unsigned pack8x4(float f0, float f1, float f2, float f3) {
    unsigned d;
    asm("{\n\t"
        ".reg .b16 lo, hi;\n\t"
        "cvt.rn.satfinite.e4m3x2.f32 lo, %2, %1;\n\t"
        "cvt.rn.satfinite.e4m3x2.f32 hi, %4, %3;\n\t"
        "mov.b32 %0, {lo, hi};\n\t"
        "}" : "=r"(d) : "f"(f0), "f"(f1), "f"(f2), "f"(f3));
    return d;
}

__device__ __forceinline__ void mma16832(float* c,
                                         unsigned a0, unsigned a1, unsigned a2, unsigned a3,
                                         unsigned b0, unsigned b1) {
    asm volatile(
        "mma.sync.aligned.m16n8k32.row.col.f32.e4m3.e4m3.f32 "
        "{%0,%1,%2,%3}, {%4,%5,%6,%7}, {%8,%9}, {%0,%1,%2,%3};"
        : "+f"(c[0]), "+f"(c[1]), "+f"(c[2]), "+f"(c[3])
        : "r"(a0), "r"(a1), "r"(a2), "r"(a3), "r"(b0), "r"(b1));
}

__device__ __forceinline__ void table_insert(int i, unsigned h) {
    unsigned long long key = ((unsigned long long)h << 6) | (unsigned long long)(i & 63);
    unsigned long long m = key * 0x9E3779B97F4A7C15ULL;
    unsigned s = (unsigned)(m >> 48);   // 16-bit slot
    for (;;) {
        unsigned long long prev = atomicCAS(&g_tkey[s], ~0ULL, key);
        if (prev == ~0ULL || prev == key) {
            atomicAdd(&g_tcnt[s], 1u);
            g_slot[i] = s;
            return;
        }
        s = (s + 1) & (TBL - 1);
    }
}

// ---------------------------------------------------------------------------
// Kernel 1 (fused): column partial sums + e4m3 fragment-order pack + inits.
//   blocks [0,512): stats+pack. Thread owns one 4-col word (P4) over 64 rows.
//   blocks [512,768): hash-table / counter init.
// Fragment layout (matches m16n8k32 A): word address (uint units) =
//   ((tile16*NG + g)*32 + (r*4 + qp))*4 + ((khalf<<1) | half8)
// where tile16=row>>4, half8=(row>>3)&1, r=row&7, g=P4>>3, qp=P4&3,
// khalf=(P4>>2)&1.  One warp LDG.128 in k_project = 512 contiguous bytes.
// ---------------------------------------------------------------------------
__global__ void k_pre(const float* __restrict__ x) {
    int b = blockIdx.x;
    if (b < 512) {
        int colblk = b & 1, stripe = b >> 1;          // 256 stripes x 64 rows
        int P4 = colblk * 256 + threadIdx.x;          // word index 0..511
        int g = P4 >> 3, qp = P4 & 3, khalf = (P4 >> 2) & 1;
        int row0 = stripe * RPS;
        const float4* src = (const float4*)x + (size_t)row0 * 512 + P4;
        float s0 = 0.f, s1 = 0.f, s2 = 0.f, s3 = 0.f;
        float q0 = 0.f, q1 = 0.f, q2 = 0.f, q3 = 0.f;
#pragma unroll 8
        for (int r = 0; r < RPS; r++) {
            int row = row0 + r;
            float4 v = src[(size_t)r * 512];
            s0 += v.x; q0 = fmaf(v.x, v.x, q0);
            s1 += v.y; q1 = fmaf(v.y, v.y, q1);
            s2 += v.z; q2 = fmaf(v.z, v.z, q2);
            s3 += v.w; q3 = fmaf(v.w, v.w, q3);
            int tile16 = row >> 4, half8 = (row >> 3) & 1, rr = row & 7;
            size_t addr = (((size_t)tile16 * NG + g) * 32 + (rr * 4 + qp)) * 4
                          + ((khalf << 1) | half8);
            g_xpack8[addr] = pack8x4(v.x, v.y, v.z, v.w);
        }
        *(float4*)(g_psum + stripe * N_FEAT + 4 * P4) = make_float4(s0, s1, s2, s3);
        *(float4*)(g_psq  + stripe * N_FEAT + 4 * P4) = make_float4(q0, q1, q2, q3);
    } else {
        int i = (b - 512) * 256 + threadIdx.x;
        g_tkey[i] = ~0ULL;
        g_tcnt[i] = 0u;
        if (b == 512 && threadIdx.x < NTILE) g_tilecnt[threadIdx.x] = 0u;
    }
}

// ---------------------------------------------------------------------------
// Kernel 2: finalize RunningMeanStd -> isig, mean*isig
// ---------------------------------------------------------------------------
__global__ void k_stats() {
    __shared__ float ss[8][32], sq[8][32];
    int c = threadIdx.x & 31, g = threadIdx.x >> 5;
    int col = blockIdx.x * 32 + c;
    float s = 0.f, q = 0.f;
    for (int st = g; st < NSTRIPE; st += 8) {
        s += g_psum[st * N_FEAT + col];
        q += g_psq [st * N_FEAT + col];
    }
    ss[g][c] = s; sq[g][c] = q;
    __syncthreads();
    if (g == 0) {
#pragma unroll
        for (int j = 1; j < 8; j++) { s += ss[j][c]; q += sq[j][c]; }
        const float n = 16384.0f;
        float bm = s / n;
        float bv = (q - bm * bm * n) / (n - 1.0f);       // unbiased variance
        const double nd = 16384.0, totd = 1e-4 + nd;
        float mean = bm * (float)(nd / totd);
        float m2v  = (1e-4f + bv * 16384.0f) + (bm * bm) * (float)(1e-4 * nd / totd);
        float var  = m2v / (float)totd;
        float isg  = 1.0f / sqrtf(var + 1e-8f);
        g_isig[col] = isg;
        g_m2[col]   = mean * isg;
    }
}

// ---------------------------------------------------------------------------
// Kernel 3: RP'' = 256*isig*RP packed e4m3x4 swizzled (blocks 0..63);
//           off[b] = 256 * sum_k m2[k]*RP[k,b] (block 64, deterministic).
// Swizzle: word (k4, n) at g_rppack8[k4*32 + (n ^ ((k4&3)<<3))].
// ---------------------------------------------------------------------------
__global__ void k_scale(const float* __restrict__ rp) {
    if (blockIdx.x < 64) {
        int idx = blockIdx.x * 256 + threadIdx.x;  // 0..16383
        int k4 = idx >> 5;                         // 4-col k word 0..511
        int n  = idx & 31;
        float f0 = rp[(4 * k4 + 0) * N_BINS + n] * g_isig[4 * k4 + 0] * 256.0f;
        float f1 = rp[(4 * k4 + 1) * N_BINS + n] * g_isig[4 * k4 + 1] * 256.0f;
        float f2 = rp[(4 * k4 + 2) * N_BINS + n] * g_isig[4 * k4 + 2] * 256.0f;
        float f3 = rp[(4 * k4 + 3) * N_BINS + n] * g_isig[4 * k4 + 3] * 256.0f;
        int scol = n ^ ((k4 & 3) << 3);
        g_rppack8[k4 * 32 + scol] = pack8x4(f0, f1, f2, f3);
    } else {
        __shared__ float red[8][32];
        int b = threadIdx.x & 31, part = threadIdx.x >> 5;   // 8 parts x 256 k
        float s = 0.f;
        for (int k = part * 256; k < part * 256 + 256; k++)
            s = fmaf(g_m2[k], rp[k * N_BINS + b], s);
        red[part][b] = s;
        __syncthreads();
        if (part == 0) {
#pragma unroll
            for (int j = 1; j < 8; j++) s += red[j][b];
            g_off[b] = s * 256.0f;
        }
    }
}

// ---------------------------------------------------------------------------
// Kernel 4: quarter-K e4m3 mma projection from fragment-packed x -> fp32
// partials -> (last arriving quarter per tile) combine + offset + sign hash
// + table insert.  512 blocks: tile = bid>>2, kq = bid&3.
// ---------------------------------------------------------------------------
__global__ void __launch_bounds__(256, 4) k_project() {
    __shared__ unsigned srp[4096];     // RP'' quarter: 128 k4-words x 32 (16KB)
    __shared__ float soff[32];
    __shared__ int s_last;

    int tile = blockIdx.x >> 2;
    int kq   = blockIdx.x & 3;

    const unsigned* rpsrc = g_rppack8 + kq * 4096;   // swizzle parity kept
    for (int idx = threadIdx.x; idx < 4096; idx += 256) srp[idx] = rpsrc[idx];
    if (threadIdx.x < 32) soff[threadIdx.x] = g_off[threadIdx.x];
    __syncthreads();

    int warp = threadIdx.x >> 5, lane = threadIdx.x & 31;
    int q = lane & 3, r = lane >> 2;
    int tile16 = tile * 8 + warp;                   // this warp's 16 rows
    int rowA = tile16 * 16 + r, rowB = rowA + 8;

    // contiguous fragment blocks: warp's uint4 lane entry per group
    const uint4* xp = (const uint4*)g_xpack8
                      + ((size_t)tile16 * NG + kq * 16) * 32 + lane;

    float acc[4][4];
#pragma unroll
    for (int t = 0; t < 4; t++)
#pragma unroll
        for (int c = 0; c < 4; c++) acc[t][c] = 0.f;

    unsigned scol[4];
#pragma unroll
    for (int t = 0; t < 4; t++) scol[t] = (unsigned)((t * 8 + r) ^ (q << 3));

#pragma unroll 4
    for (int g = 0; g < 16; g++) {                  // 16 groups of 32 k-cols
        uint4 a = xp[g * 32];                       // a0..a3 fragment regs
        int w0 = (g * 8 + q) * 32;
        int w1 = (g * 8 + q + 4) * 32;
#pragma unroll
        for (int t = 0; t < 4; t++) {
            unsigned b0 = srp[w0 + scol[t]];
            unsigned b1 = srp[w1 + scol[t]];
            mma16832(acc[t], a.x, a.y, a.z, a.w, b0, b1);
        }
    }

    // publish my quarter's partials
    float* dst = g_part + (size_t)kq * N_ROWS * N_BINS;
#pragma unroll
    for (int t = 0; t < 4; t++) {
        int cb = t * 8 + 2 * q;
        *(float2*)(dst + (size_t)rowA * N_BINS + cb) = make_float2(acc[t][0], acc[t][1]);
        *(float2*)(dst + (size_t)rowB * N_BINS + cb) = make_float2(acc[t][2], acc[t][3]);
    }
    __threadfence();
    if (threadIdx.x == 0) s_last = (int)atomicAdd(&g_tilecnt[tile], 1u);
    __syncthreads();
    if (s_last != NKQ - 1) return;    // earlier arrivals are done
    __threadfence();                  // make peers' partials visible

    // last-arriving quarter: add 3 peer partials (L2), subtract offset, sign
    unsigned mlo = 0u, mhi = 0u;
#pragma unroll
    for (int t = 0; t < 4; t++) {
        int cb = t * 8 + 2 * q;
        float sA0 = acc[t][0], sA1 = acc[t][1];
        float sB0 = acc[t][2], sB1 = acc[t][3];
#pragma unroll
        for (int o = 0; o < NKQ; o++) {
            if (o == kq) continue;
            const float* src = g_part + (size_t)o * N_ROWS * N_BINS;
            float2 pa = *(const float2*)(src + (size_t)rowA * N_BINS + cb);
            float2 pb = *(const float2*)(src + (size_t)rowB * N_BINS + cb);
            sA0 += pa.x; sA1 += pa.y;
            sB0 += pb.x; sB1 += pb.y;
        }
        float o0 = soff[cb], o1 = soff[cb + 1];
        mlo |= ((sA0 - o0) > 0.f ? 1u : 0u) << cb;
        mlo |= ((sA1 - o1) > 0.f ? 1u : 0u) << (cb + 1);
        mhi |= ((sB0 - o0) > 0.f ? 1u : 0u) << cb;
        mhi |= ((sB1 - o1) > 0.f ? 1u : 0u) << (cb + 1);
    }
    mlo |= __shfl_xor_sync(0xffffffffu, mlo, 1);
    mlo |= __shfl_xor_sync(0xffffffffu, mlo, 2);
    mhi |= __shfl_xor_sync(0xffffffffu, mhi, 1);
    mhi |= __shfl_xor_sync(0xffffffffu, mhi, 2);

    if (q == 0) {
        g_hash[rowA] = mlo;
        g_hash[rowB] = mhi;
        table_insert(rowA, mlo);
        table_insert(rowB, mhi);
    }
}

// ---------------------------------------------------------------------------
// Kernel 5: rewards. Unique keys -> 1.0; rare duplicates get exact rank.
// ---------------------------------------------------------------------------
__global__ void k_final(float* __restrict__ out) {
    int i = blockIdx.x * 128 + threadIdx.x;
    unsigned s = g_slot[i];
    float v = 1.0f;
    if (g_tcnt[s] != 1u) {
        unsigned long long my = ((unsigned long long)g_hash[i] << 6) | (unsigned long long)(i & 63);
        int c = 1;
        for (int j = 0; j < i; j++) {
            unsigned long long kj = ((unsigned long long)g_hash[j] << 6) | (unsigned long long)(j & 63);
            c += (kj == my) ? 1 : 0;
        }
        v = 1.0f / sqrtf((float)c);
    }
    out[i] = v;
}

// ---------------------------------------------------------------------------
// Launch
// ---------------------------------------------------------------------------
extern "C" void kernel_launch(void* const* d_in, const int* in_sizes, int n_in,
                              void* d_out, int out_size) {
    const float* x  = (const float*)d_in[0];
    const float* rp = (const float*)d_in[1];
    if (in_sizes[0] == N_FEAT * N_BINS) {   // defensive: swap if order differs
        const float* t = x; x = rp; rp = t;
    }
    float* out = (float*)d_out;

    k_pre    <<<768, 256>>>(x);
    k_stats  <<<64, 256>>>();
    k_scale  <<<65, 256>>>(rp);
    k_project<<<512, 256>>>();
    k_final  <<<128, 128>>>(out);
}